// round 1
// baseline (speedup 1.0000x reference)
#include <cuda_runtime.h>
#include <math.h>

#define TOK 4096
#define DIM 1024
#define HID 1024
#define NE  16
#define SHH 2048

#define BM 64
#define BN 64
#define BK 16
#define NTHR 128

// Scratch (static __device__ globals: allocation-free, graph-safe)
__device__ int   g_cnt[NE];
__device__ int   g_list[NE * TOK];           // packed entry: token*2 + slot
__device__ float g_lw[NE * TOK];             // routing weight per entry
__device__ float g_hbuf[(size_t)TOK * 2 * HID];  // 32MB: SwiGLU hidden per (t,k)
__device__ float g_zbuf[(size_t)TOK * SHH];      // 32MB: shared-expert hidden

__global__ void k_zero() { if (threadIdx.x < NE) g_cnt[threadIdx.x] = 0; }

// ---------------------------------------------------------------------------
// Gate: one warp per token. scores = emb @ gate_w^T, softmax, top-2, scatter
// into per-expert lists with routing weights.
// ---------------------------------------------------------------------------
__global__ void k_gate(const float* __restrict__ emb, const float* __restrict__ gw)
{
    int t    = (blockIdx.x * blockDim.x + threadIdx.x) >> 5;
    int lane = threadIdx.x & 31;
    if (t >= TOK) return;
    const float* row = emb + (size_t)t * DIM;
    float xr[32];
#pragma unroll
    for (int i = 0; i < 32; i++) xr[i] = row[lane + 32 * i];
    float sc[NE];
#pragma unroll
    for (int e = 0; e < NE; e++) {
        const float* g = gw + e * DIM;
        float acc = 0.f;
#pragma unroll
        for (int i = 0; i < 32; i++) acc += xr[i] * g[lane + 32 * i];
#pragma unroll
        for (int o = 16; o > 0; o >>= 1) acc += __shfl_xor_sync(0xffffffffu, acc, o);
        sc[e] = acc;
    }
    if (lane == 0) {
        float m = sc[0];
#pragma unroll
        for (int e = 1; e < NE; e++) m = fmaxf(m, sc[e]);
        float s = 0.f;
#pragma unroll
        for (int e = 0; e < NE; e++) { sc[e] = expf(sc[e] - m); s += sc[e]; }
        float inv = 1.f / s;
        int i0 = 0;
#pragma unroll
        for (int e = 1; e < NE; e++) if (sc[e] > sc[i0]) i0 = e;   // ties -> lowest idx
        int i1 = (i0 == 0) ? 1 : 0;
#pragma unroll
        for (int e = 0; e < NE; e++) if (e != i0 && sc[e] > sc[i1]) i1 = e;
        int p0 = atomicAdd(&g_cnt[i0], 1);
        g_list[i0 * TOK + p0] = t * 2;
        g_lw  [i0 * TOK + p0] = sc[i0] * inv;
        int p1 = atomicAdd(&g_cnt[i1], 1);
        g_list[i1 * TOK + p1] = t * 2 + 1;
        g_lw  [i1 * TOK + p1] = sc[i1] * inv;
    }
}

// ---------------------------------------------------------------------------
// Routed dual-GEMM: for expert e, gathered tokens -> W1 and W3 products in one
// pass (shared A tile), SwiGLU epilogue into g_hbuf[(t*2+k)*HID].
// ---------------------------------------------------------------------------
__global__ void k_moe1(const float* __restrict__ x, const float* __restrict__ emb,
                       const float* __restrict__ W1, const float* __restrict__ B1,
                       const float* __restrict__ W3, const float* __restrict__ B3)
{
    int e   = blockIdx.z;
    int cnt = g_cnt[e];
    int r0  = blockIdx.y * BM;
    if (r0 >= cnt) return;
    int c0  = blockIdx.x * BN;

    __shared__ float As [BK][BM];
    __shared__ float B1s[BK][BN];
    __shared__ float B3s[BK][BN];
    __shared__ int   rs [BM];

    int tid = threadIdx.x;
    if (tid < BM) rs[tid] = (r0 + tid < cnt) ? g_list[e * TOK + r0 + tid] : -1;
    __syncthreads();

    const float* src = (e < 2) ? x : emb;
    int ar = tid >> 1, ac = (tid & 1) * 8;
    int enta = rs[ar];
    bool aval = (enta >= 0);
    const float* arow = aval ? src + (size_t)(enta >> 1) * DIM : src;

    int br = tid >> 3, bc = (tid & 7) * 8;
    const float* w1p = W1 + (size_t)e * DIM * HID + c0 + bc;
    const float* w3p = W3 + (size_t)e * DIM * HID + c0 + bc;

    int ty = tid >> 3, tx = tid & 7;
    float acc1[4][8] = {}, acc3[4][8] = {};

    for (int kb = 0; kb < DIM; kb += BK) {
        if (aval) {
            float4 v0 = *(const float4*)(arow + kb + ac);
            float4 v1 = *(const float4*)(arow + kb + ac + 4);
            As[ac+0][ar]=v0.x; As[ac+1][ar]=v0.y; As[ac+2][ar]=v0.z; As[ac+3][ar]=v0.w;
            As[ac+4][ar]=v1.x; As[ac+5][ar]=v1.y; As[ac+6][ar]=v1.z; As[ac+7][ar]=v1.w;
        } else {
#pragma unroll
            for (int j = 0; j < 8; j++) As[ac+j][ar] = 0.f;
        }
        const float* p1 = w1p + (size_t)(kb + br) * HID;
        *(float4*)&B1s[br][bc]     = *(const float4*)(p1);
        *(float4*)&B1s[br][bc + 4] = *(const float4*)(p1 + 4);
        const float* p3 = w3p + (size_t)(kb + br) * HID;
        *(float4*)&B3s[br][bc]     = *(const float4*)(p3);
        *(float4*)&B3s[br][bc + 4] = *(const float4*)(p3 + 4);
        __syncthreads();
#pragma unroll
        for (int k = 0; k < BK; k++) {
            float a[4];
#pragma unroll
            for (int i = 0; i < 4; i++) a[i] = As[k][ty*4 + i];
            float b1v[8], b3v[8];
            *(float4*)&b1v[0] = *(float4*)&B1s[k][tx*8];
            *(float4*)&b1v[4] = *(float4*)&B1s[k][tx*8 + 4];
            *(float4*)&b3v[0] = *(float4*)&B3s[k][tx*8];
            *(float4*)&b3v[4] = *(float4*)&B3s[k][tx*8 + 4];
#pragma unroll
            for (int i = 0; i < 4; i++)
#pragma unroll
                for (int j = 0; j < 8; j++) {
                    acc1[i][j] += a[i] * b1v[j];
                    acc3[i][j] += a[i] * b3v[j];
                }
        }
        __syncthreads();
    }

    float bb1[8], bb3[8];
#pragma unroll
    for (int j = 0; j < 8; j++) {
        bb1[j] = B1[e * HID + c0 + tx*8 + j];
        bb3[j] = B3[e * HID + c0 + tx*8 + j];
    }
#pragma unroll
    for (int i = 0; i < 4; i++) {
        int ent = rs[ty*4 + i];
        if (ent < 0) continue;
        float* hp = g_hbuf + (size_t)ent * HID + c0 + tx*8;
#pragma unroll
        for (int j = 0; j < 8; j++) {
            float u = acc1[i][j] + bb1[j];
            float v = acc3[i][j] + bb3[j];
            hp[j] = (u / (1.f + expf(-u))) * v;     // silu(u) * v
        }
    }
}

// ---------------------------------------------------------------------------
// Routed GEMM2: g_hbuf rows @ W2[e], scaled by routing weight, atomicAdd into
// out (which already holds the shared-expert result z).
// ---------------------------------------------------------------------------
__global__ void k_moe2(const float* __restrict__ W2, const float* __restrict__ B2,
                       float* __restrict__ out)
{
    int e   = blockIdx.z;
    int cnt = g_cnt[e];
    int r0  = blockIdx.y * BM;
    if (r0 >= cnt) return;
    int c0  = blockIdx.x * BN;

    __shared__ float As[BK][BM];
    __shared__ float Bs[BK][BN];
    __shared__ int   rs[BM];
    __shared__ float ws[BM];

    int tid = threadIdx.x;
    if (tid < BM) {
        int idx = r0 + tid;
        rs[tid] = (idx < cnt) ? g_list[e * TOK + idx] : -1;
        ws[tid] = (idx < cnt) ? g_lw [e * TOK + idx] : 0.f;
    }
    __syncthreads();

    int ar = tid >> 1, ac = (tid & 1) * 8;
    int enta = rs[ar];
    bool aval = (enta >= 0);
    const float* arow = aval ? g_hbuf + (size_t)enta * HID : g_hbuf;

    int br = tid >> 3, bc = (tid & 7) * 8;
    const float* wp = W2 + (size_t)e * HID * DIM + c0 + bc;

    int ty = tid >> 3, tx = tid & 7;
    float acc[4][8] = {};

    for (int kb = 0; kb < HID; kb += BK) {
        if (aval) {
            float4 v0 = *(const float4*)(arow + kb + ac);
            float4 v1 = *(const float4*)(arow + kb + ac + 4);
            As[ac+0][ar]=v0.x; As[ac+1][ar]=v0.y; As[ac+2][ar]=v0.z; As[ac+3][ar]=v0.w;
            As[ac+4][ar]=v1.x; As[ac+5][ar]=v1.y; As[ac+6][ar]=v1.z; As[ac+7][ar]=v1.w;
        } else {
#pragma unroll
            for (int j = 0; j < 8; j++) As[ac+j][ar] = 0.f;
        }
        const float* p = wp + (size_t)(kb + br) * DIM;
        *(float4*)&Bs[br][bc]     = *(const float4*)(p);
        *(float4*)&Bs[br][bc + 4] = *(const float4*)(p + 4);
        __syncthreads();
#pragma unroll
        for (int k = 0; k < BK; k++) {
            float a[4];
#pragma unroll
            for (int i = 0; i < 4; i++) a[i] = As[k][ty*4 + i];
            float bv[8];
            *(float4*)&bv[0] = *(float4*)&Bs[k][tx*8];
            *(float4*)&bv[4] = *(float4*)&Bs[k][tx*8 + 4];
#pragma unroll
            for (int i = 0; i < 4; i++)
#pragma unroll
                for (int j = 0; j < 8; j++) acc[i][j] += a[i] * bv[j];
        }
        __syncthreads();
    }

    float bb[8];
#pragma unroll
    for (int j = 0; j < 8; j++) bb[j] = B2[e * DIM + c0 + tx*8 + j];
#pragma unroll
    for (int i = 0; i < 4; i++) {
        int ent = rs[ty*4 + i];
        if (ent < 0) continue;
        int t = ent >> 1;
        float w = ws[ty*4 + i];
        float* op = out + (size_t)t * DIM + c0 + tx*8;
#pragma unroll
        for (int j = 0; j < 8; j++) atomicAdd(&op[j], w * (acc[i][j] + bb[j]));
    }
}

// ---------------------------------------------------------------------------
// Shared expert GEMM1: zbuf = silu(emb @ sW1 + sB1)   [TOK, SHH]
// ---------------------------------------------------------------------------
__global__ void k_s1(const float* __restrict__ emb, const float* __restrict__ sW1,
                     const float* __restrict__ sB1)
{
    int r0 = blockIdx.y * BM, c0 = blockIdx.x * BN;
    __shared__ float As[BK][BM];
    __shared__ float Bs[BK][BN];
    int tid = threadIdx.x;
    int ar = tid >> 1, ac = (tid & 1) * 8;
    const float* arow = emb + (size_t)(r0 + ar) * DIM;
    int br = tid >> 3, bc = (tid & 7) * 8;
    const float* wp = sW1 + c0 + bc;
    int ty = tid >> 3, tx = tid & 7;
    float acc[4][8] = {};

    for (int kb = 0; kb < DIM; kb += BK) {
        float4 v0 = *(const float4*)(arow + kb + ac);
        float4 v1 = *(const float4*)(arow + kb + ac + 4);
        As[ac+0][ar]=v0.x; As[ac+1][ar]=v0.y; As[ac+2][ar]=v0.z; As[ac+3][ar]=v0.w;
        As[ac+4][ar]=v1.x; As[ac+5][ar]=v1.y; As[ac+6][ar]=v1.z; As[ac+7][ar]=v1.w;
        const float* p = wp + (size_t)(kb + br) * SHH;
        *(float4*)&Bs[br][bc]     = *(const float4*)(p);
        *(float4*)&Bs[br][bc + 4] = *(const float4*)(p + 4);
        __syncthreads();
#pragma unroll
        for (int k = 0; k < BK; k++) {
            float a[4];
#pragma unroll
            for (int i = 0; i < 4; i++) a[i] = As[k][ty*4 + i];
            float bv[8];
            *(float4*)&bv[0] = *(float4*)&Bs[k][tx*8];
            *(float4*)&bv[4] = *(float4*)&Bs[k][tx*8 + 4];
#pragma unroll
            for (int i = 0; i < 4; i++)
#pragma unroll
                for (int j = 0; j < 8; j++) acc[i][j] += a[i] * bv[j];
        }
        __syncthreads();
    }

    float bb[8];
#pragma unroll
    for (int j = 0; j < 8; j++) bb[j] = sB1[c0 + tx*8 + j];
#pragma unroll
    for (int i = 0; i < 4; i++) {
        float* zp = g_zbuf + (size_t)(r0 + ty*4 + i) * SHH + c0 + tx*8;
#pragma unroll
        for (int j = 0; j < 8; j++) {
            float u = acc[i][j] + bb[j];
            zp[j] = u / (1.f + expf(-u));           // silu
        }
    }
}

// ---------------------------------------------------------------------------
// Shared expert GEMM2: out = zbuf @ sW2 + sB2 (plain store — initializes out)
// ---------------------------------------------------------------------------
__global__ void k_s2(const float* __restrict__ sW2, const float* __restrict__ sB2,
                     float* __restrict__ out)
{
    int r0 = blockIdx.y * BM, c0 = blockIdx.x * BN;
    __shared__ float As[BK][BM];
    __shared__ float Bs[BK][BN];
    int tid = threadIdx.x;
    int ar = tid >> 1, ac = (tid & 1) * 8;
    const float* arow = g_zbuf + (size_t)(r0 + ar) * SHH;
    int br = tid >> 3, bc = (tid & 7) * 8;
    const float* wp = sW2 + c0 + bc;
    int ty = tid >> 3, tx = tid & 7;
    float acc[4][8] = {};

    for (int kb = 0; kb < SHH; kb += BK) {
        float4 v0 = *(const float4*)(arow + kb + ac);
        float4 v1 = *(const float4*)(arow + kb + ac + 4);
        As[ac+0][ar]=v0.x; As[ac+1][ar]=v0.y; As[ac+2][ar]=v0.z; As[ac+3][ar]=v0.w;
        As[ac+4][ar]=v1.x; As[ac+5][ar]=v1.y; As[ac+6][ar]=v1.z; As[ac+7][ar]=v1.w;
        const float* p = wp + (size_t)(kb + br) * DIM;
        *(float4*)&Bs[br][bc]     = *(const float4*)(p);
        *(float4*)&Bs[br][bc + 4] = *(const float4*)(p + 4);
        __syncthreads();
#pragma unroll
        for (int k = 0; k < BK; k++) {
            float a[4];
#pragma unroll
            for (int i = 0; i < 4; i++) a[i] = As[k][ty*4 + i];
            float bv[8];
            *(float4*)&bv[0] = *(float4*)&Bs[k][tx*8];
            *(float4*)&bv[4] = *(float4*)&Bs[k][tx*8 + 4];
#pragma unroll
            for (int i = 0; i < 4; i++)
#pragma unroll
                for (int j = 0; j < 8; j++) acc[i][j] += a[i] * bv[j];
        }
        __syncthreads();
    }

    float bb[8];
#pragma unroll
    for (int j = 0; j < 8; j++) bb[j] = sB2[c0 + tx*8 + j];
#pragma unroll
    for (int i = 0; i < 4; i++) {
        float* op = out + (size_t)(r0 + ty*4 + i) * DIM + c0 + tx*8;
#pragma unroll
        for (int j = 0; j < 8; j++) op[j] = acc[i][j] + bb[j];
    }
}

// ---------------------------------------------------------------------------
extern "C" void kernel_launch(void* const* d_in, const int* in_sizes, int n_in,
                              void* d_out, int out_size)
{
    const float* emb = (const float*)d_in[0];
    const float* x   = (const float*)d_in[1];
    const float* gw  = (const float*)d_in[2];
    const float* W1  = (const float*)d_in[3];
    const float* B1  = (const float*)d_in[4];
    const float* W2  = (const float*)d_in[5];
    const float* B2  = (const float*)d_in[6];
    const float* W3  = (const float*)d_in[7];
    const float* B3  = (const float*)d_in[8];
    const float* sW1 = (const float*)d_in[9];
    const float* sB1 = (const float*)d_in[10];
    const float* sW2 = (const float*)d_in[11];
    const float* sB2 = (const float*)d_in[12];
    float* out = (float*)d_out;

    k_zero<<<1, 32>>>();
    k_gate<<<TOK / 4, 128>>>(emb, gw);
    // Shared expert first: k_s2 plain-stores out = z, then routed atomics add y.
    k_s1<<<dim3(SHH / BN, TOK / BM), NTHR>>>(emb, sW1, sB1);
    k_s2<<<dim3(DIM / BN, TOK / BM), NTHR>>>(sW2, sB2, out);
    k_moe1<<<dim3(HID / BN, TOK / BM, NE), NTHR>>>(x, emb, W1, B1, W3, B3);
    k_moe2<<<dim3(DIM / BN, TOK / BM, NE), NTHR>>>(W2, B2, out);
    (void)in_sizes; (void)n_in; (void)out_size;
}

// round 3
// speedup vs baseline: 4.9955x; 4.9955x over previous
#include <cuda_runtime.h>
#include <cstdint>
#include <math.h>

#define TOK 4096
#define DIM 1024
#define HID 1024
#define NE  16
#define SHH 2048

#define BMT 128      // CTA tile M
#define BNT 128      // CTA tile N
#define KC  32       // K chunk
#define ABUF 16384   // one A (or B) tile: 128 rows x 32 f32 = 16KB
#define BUFB 32768   // A+B per stage
#define SMEM_GEMM (2*BUFB + 1024)

// ---------------- scratch (__device__ globals: allocation-free) -------------
__device__ int   g_cnt[NE];
__device__ int   g_list[NE * TOK];                // packed entry: token*2 + slot
__device__ float g_went[TOK * 2];                 // routing weight per entry
__device__ float g_embr[(size_t)TOK * DIM];       // tf32-rounded embeddings
__device__ float g_xr[(size_t)TOK * DIM];         // tf32-rounded x
__device__ float g_ubuf[(size_t)TOK * 2 * HID];   // W1 products, later expert outputs
__device__ float g_hbuf[(size_t)TOK * 2 * HID];   // W3 products, later SwiGLU hidden
__device__ float g_zbuf[(size_t)TOK * SHH];       // shared-expert hidden
__device__ float g_tw1[(size_t)NE * DIM * HID];   // W1^T [e][h][d] (tf32)
__device__ float g_tw3[(size_t)NE * DIM * HID];   // W3^T [e][h][d]
__device__ float g_tw2[(size_t)NE * DIM * HID];   // W2^T [e][d][h]
__device__ float g_tsw1[(size_t)SHH * DIM];       // sW1^T [h][d]
__device__ float g_tsw2[(size_t)DIM * SHH];       // sW2^T [d][h]

// ---------------- helpers ----------------------------------------------------
__device__ __forceinline__ uint32_t smem_u32(const void* p) {
    uint32_t a;
    asm("{ .reg .u64 t; cvta.to.shared.u64 t, %1; cvt.u32.u64 %0, t; }"
        : "=r"(a) : "l"(p));
    return a;
}
__device__ __forceinline__ float rtf(float x) {        // round-to-nearest tf32
    uint32_t u;
    asm("cvt.rna.tf32.f32 %0, %1;" : "=r"(u) : "f"(x));
    return __uint_as_float(u);
}
__device__ __forceinline__ uint32_t swz(uint32_t o) {  // XOR bits[4:6] ^= row[0:2]
    return o ^ (((o >> 7) & 7u) << 4);
}
__device__ __forceinline__ void cp16(uint32_t d, const void* s) {
    asm volatile("cp.async.cg.shared.global [%0], [%1], 16;" :: "r"(d), "l"(s));
}
__device__ __forceinline__ void cp16z(uint32_t d, const void* s, uint32_t n) {
    asm volatile("cp.async.cg.shared.global [%0], [%1], 16, %2;" :: "r"(d), "l"(s), "r"(n));
}
__device__ __forceinline__ void cp_commit() { asm volatile("cp.async.commit_group;"); }
__device__ __forceinline__ void cp_wait1()  { asm volatile("cp.async.wait_group 1;"); }
__device__ __forceinline__ void cp_wait0()  { asm volatile("cp.async.wait_group 0;"); }

__device__ __forceinline__ void ldsm4(uint32_t* r, uint32_t a) {
    asm volatile("ldmatrix.sync.aligned.m8n8.x4.shared.b16 {%0,%1,%2,%3}, [%4];"
                 : "=r"(r[0]), "=r"(r[1]), "=r"(r[2]), "=r"(r[3]) : "r"(a));
}
__device__ __forceinline__ void mma8(float* d, const uint32_t* a, uint32_t b0, uint32_t b1) {
    asm volatile("mma.sync.aligned.m16n8k8.row.col.f32.tf32.tf32.f32 "
                 "{%0,%1,%2,%3}, {%4,%5,%6,%7}, {%8,%9}, {%0,%1,%2,%3};"
                 : "+f"(d[0]), "+f"(d[1]), "+f"(d[2]), "+f"(d[3])
                 : "r"(a[0]), "r"(a[1]), "r"(a[2]), "r"(a[3]), "r"(b0), "r"(b1));
}

struct MMCtx {
    const float* a_src[4];
    const float* b_src[4];
    uint32_t     dst[4];     // swizzled byte offset inside a tile (same for A and B)
    uint32_t     a_sz[4];    // 16 or 0 (zero-fill for padded rows)
};

__device__ __forceinline__ void mm_setup_dst(MMCtx& cx, int tid) {
    int chunk = tid & 7, rb = tid >> 3;
#pragma unroll
    for (int i = 0; i < 4; i++) {
        int row = rb + 32 * i;
        cx.dst[i] = swz((uint32_t)row * 128u + (uint32_t)chunk * 16u);
    }
}
__device__ __forceinline__ void mm_issue(const MMCtx& cx, uint32_t sb, int buf, int c) {
    uint32_t ab = sb + buf * BUFB, bb = ab + ABUF;
#pragma unroll
    for (int i = 0; i < 4; i++) cp16z(ab + cx.dst[i], cx.a_src[i] + c * KC, cx.a_sz[i]);
#pragma unroll
    for (int i = 0; i < 4; i++) cp16(bb + cx.dst[i], cx.b_src[i] + c * KC);
    cp_commit();
}
__device__ __forceinline__ void mm_compute(uint32_t ab, uint32_t bb,
                                           float acc[2][8][4], int lane, int wm, int wn) {
#pragma unroll
    for (int ks = 0; ks < 4; ks++) {
        int k0 = ks * 8;
        uint32_t a[2][4];
#pragma unroll
        for (int mi = 0; mi < 2; mi++) {
            int row = wm * 32 + mi * 16 + (lane & 15);
            uint32_t o = (uint32_t)row * 128u + (uint32_t)(k0 + ((lane & 16) >> 2)) * 4u;
            ldsm4(a[mi], ab + swz(o));
        }
#pragma unroll
        for (int p = 0; p < 4; p++) {
            int rowN = wn * 64 + p * 16 + (lane & 7) + ((lane & 16) >> 1);
            uint32_t o = (uint32_t)rowN * 128u + (uint32_t)(k0 + ((lane & 8) >> 1)) * 4u;
            uint32_t bf[4];
            ldsm4(bf, bb + swz(o));
            mma8(acc[0][2*p],   a[0], bf[0], bf[1]);
            mma8(acc[1][2*p],   a[1], bf[0], bf[1]);
            mma8(acc[0][2*p+1], a[0], bf[2], bf[3]);
            mma8(acc[1][2*p+1], a[1], bf[2], bf[3]);
        }
    }
}
__device__ __forceinline__ void mm_loop(const MMCtx& cx, uint32_t sb, int K,
                                        float acc[2][8][4], int lane, int wm, int wn) {
    int NCH = K / KC;
    mm_issue(cx, sb, 0, 0);
    for (int c = 0; c < NCH; c++) {
        int b = c & 1;
        if (c + 1 < NCH) { mm_issue(cx, sb, b ^ 1, c + 1); cp_wait1(); }
        else             { cp_wait0(); }
        __syncthreads();
        mm_compute(sb + b * BUFB, sb + b * BUFB + ABUF, acc, lane, wm, wn);
        __syncthreads();
    }
}

// ---------------- small kernels -----------------------------------------------
__global__ void k_zero() { if (threadIdx.x < NE) g_cnt[threadIdx.x] = 0; }

__global__ void k_round(const float* __restrict__ s, float* __restrict__ d, int n4) {
    int i = blockIdx.x * blockDim.x + threadIdx.x;
    if (i < n4) {
        float4 v = ((const float4*)s)[i];
        ((float4*)d)[i] = make_float4(rtf(v.x), rtf(v.y), rtf(v.z), rtf(v.w));
    }
}

__global__ void k_gate(const float* __restrict__ emb, const float* __restrict__ gw)
{
    int t = (blockIdx.x * blockDim.x + threadIdx.x) >> 5;
    int lane = threadIdx.x & 31;
    if (t >= TOK) return;
    const float* row = emb + (size_t)t * DIM;
    float xr[32];
#pragma unroll
    for (int i = 0; i < 32; i++) xr[i] = row[lane + 32 * i];
    float sc[NE];
#pragma unroll
    for (int e = 0; e < NE; e++) {
        const float* g = gw + e * DIM;
        float acc = 0.f;
#pragma unroll
        for (int i = 0; i < 32; i++) acc += xr[i] * g[lane + 32 * i];
#pragma unroll
        for (int o = 16; o > 0; o >>= 1) acc += __shfl_xor_sync(0xffffffffu, acc, o);
        sc[e] = acc;
    }
    if (lane == 0) {
        float m = sc[0];
#pragma unroll
        for (int e = 1; e < NE; e++) m = fmaxf(m, sc[e]);
        float s = 0.f;
#pragma unroll
        for (int e = 0; e < NE; e++) { sc[e] = expf(sc[e] - m); s += sc[e]; }
        float inv = 1.f / s;
        int i0 = 0;
#pragma unroll
        for (int e = 1; e < NE; e++) if (sc[e] > sc[i0]) i0 = e;
        int i1 = (i0 == 0) ? 1 : 0;
#pragma unroll
        for (int e = 0; e < NE; e++) if (e != i0 && sc[e] > sc[i1]) i1 = e;
        int p0 = atomicAdd(&g_cnt[i0], 1);
        g_list[i0 * TOK + p0] = t * 2;
        g_went[t * 2] = sc[i0] * inv;
        int p1 = atomicAdd(&g_cnt[i1], 1);
        g_list[i1 * TOK + p1] = t * 2 + 1;
        g_went[t * 2 + 1] = sc[i1] * inv;
    }
}

// transpose + tf32 round: dst[b][c][r] = rna(src[b][r][c])
__global__ void k_tr(const float* __restrict__ src, float* __restrict__ dst, int R, int C)
{
    __shared__ float t[32][33];
    size_t boff = (size_t)blockIdx.z * R * C;
    int c0 = blockIdx.x * 32, r0 = blockIdx.y * 32;
    int tx = threadIdx.x, ty = threadIdx.y;
#pragma unroll
    for (int i = 0; i < 32; i += 8)
        t[ty + i][tx] = src[boff + (size_t)(r0 + ty + i) * C + c0 + tx];
    __syncthreads();
#pragma unroll
    for (int i = 0; i < 32; i += 8)
        dst[boff + (size_t)(c0 + ty + i) * R + r0 + tx] = rtf(t[tx][ty + i]);
}

// ---------------- dense GEMM (shared expert): EPI 0 = +bias store, 1 = silu+rtf
template<int EPI>
__global__ void __launch_bounds__(256, 2) k_dense(
    const float* __restrict__ A, int lda,
    const float* __restrict__ Bw, int K,
    const float* __restrict__ bias,
    float* __restrict__ C, int ldc)
{
    extern __shared__ char dsm[];
    uint32_t sb = (smem_u32(dsm) + 127u) & ~127u;
    int tid = threadIdx.x, lane = tid & 31, w = tid >> 5;
    int wm = w & 3, wn = w >> 2;
    int r0 = blockIdx.y * BMT, c0 = blockIdx.x * BNT;

    MMCtx cx;
    mm_setup_dst(cx, tid);
    {
        int chunk = tid & 7, rb = tid >> 3;
#pragma unroll
        for (int i = 0; i < 4; i++) {
            int row = rb + 32 * i;
            cx.a_src[i] = A + (size_t)(r0 + row) * lda + chunk * 4;
            cx.a_sz[i] = 16;
            cx.b_src[i] = Bw + (size_t)(c0 + row) * K + chunk * 4;
        }
    }
    float acc[2][8][4] = {};
    mm_loop(cx, sb, K, acc, lane, wm, wn);

    int g = lane >> 2, t = lane & 3;
#pragma unroll
    for (int mi = 0; mi < 2; mi++)
#pragma unroll
        for (int h = 0; h < 2; h++) {
            int row = r0 + wm * 32 + mi * 16 + g + h * 8;
#pragma unroll
            for (int nj = 0; nj < 8; nj++) {
                int col = c0 + wn * 64 + nj * 8 + 2 * t;
                float v0 = acc[mi][nj][h * 2 + 0] + bias[col];
                float v1 = acc[mi][nj][h * 2 + 1] + bias[col + 1];
                if (EPI == 1) {
                    v0 = rtf(v0 / (1.f + __expf(-v0)));
                    v1 = rtf(v1 / (1.f + __expf(-v1)));
                }
                *(float2*)(C + (size_t)row * ldc + col) = make_float2(v0, v1);
            }
        }
}

// ---------------- routed GEMM: GM 0 = gather tokens (ent>>1, x/emb), GM 1 = gather hbuf rows
template<int GM>
__global__ void __launch_bounds__(256, 2) k_moe(
    const float* __restrict__ p0, const float* __restrict__ p1,
    const float* __restrict__ Bw_all, int K,
    const float* __restrict__ bias_all,
    float* __restrict__ C, int ldc)
{
    int e = blockIdx.z;
    int cnt = g_cnt[e];
    int r0 = blockIdx.y * BMT;
    if (r0 >= cnt) return;
    int c0 = blockIdx.x * BNT;

    extern __shared__ char dsm[];
    __shared__ int rs[BMT];
    uint32_t sb = (smem_u32(dsm) + 127u) & ~127u;
    int tid = threadIdx.x, lane = tid & 31, w = tid >> 5;
    int wm = w & 3, wn = w >> 2;

    if (tid < BMT) rs[tid] = (r0 + tid < cnt) ? g_list[e * TOK + r0 + tid] : -1;
    __syncthreads();

    MMCtx cx;
    mm_setup_dst(cx, tid);
    {
        int chunk = tid & 7, rb = tid >> 3;
        const float* base = (GM == 0) ? ((e < 2) ? p0 : p1) : p0;
#pragma unroll
        for (int i = 0; i < 4; i++) {
            int row = rb + 32 * i;
            int ent = rs[row];
            bool v = (ent >= 0);
            if (GM == 0)
                cx.a_src[i] = v ? base + (size_t)(ent >> 1) * DIM + chunk * 4 : base;
            else
                cx.a_src[i] = v ? base + (size_t)ent * HID + chunk * 4 : base;
            cx.a_sz[i] = v ? 16 : 0;
            cx.b_src[i] = Bw_all + ((size_t)e * ldc + c0 + row) * K + chunk * 4;
        }
    }
    float acc[2][8][4] = {};
    mm_loop(cx, sb, K, acc, lane, wm, wn);

    const float* bias = bias_all + (size_t)e * ldc;
    int g = lane >> 2, t = lane & 3;
#pragma unroll
    for (int mi = 0; mi < 2; mi++)
#pragma unroll
        for (int h = 0; h < 2; h++) {
            int lr = wm * 32 + mi * 16 + g + h * 8;
            int ent = rs[lr];
            if (ent < 0) continue;
#pragma unroll
            for (int nj = 0; nj < 8; nj++) {
                int col = c0 + wn * 64 + nj * 8 + 2 * t;
                float v0 = acc[mi][nj][h * 2 + 0] + bias[col];
                float v1 = acc[mi][nj][h * 2 + 1] + bias[col + 1];
                *(float2*)(C + (size_t)ent * ldc + col) = make_float2(v0, v1);
            }
        }
}

// ---------------- SwiGLU combine: hbuf = rtf(silu(ubuf) * hbuf) ---------------
__global__ void k_swiglu(int n4) {
    int i = blockIdx.x * blockDim.x + threadIdx.x;
    if (i >= n4) return;
    float4 u = ((const float4*)g_ubuf)[i];
    float4 v = ((float4*)g_hbuf)[i];
    float4 o;
    o.x = rtf((u.x / (1.f + __expf(-u.x))) * v.x);
    o.y = rtf((u.y / (1.f + __expf(-u.y))) * v.y);
    o.z = rtf((u.z / (1.f + __expf(-u.z))) * v.z);
    o.w = rtf((u.w / (1.f + __expf(-u.w))) * v.w);
    ((float4*)g_hbuf)[i] = o;
}

// ---------------- final combine: out[t] += w0*o[2t] + w1*o[2t+1] ---------------
__global__ void k_comb(float* __restrict__ out) {
    int t = blockIdx.x;
    int d = threadIdx.x * 4;
    float w0 = g_went[t * 2], w1 = g_went[t * 2 + 1];
    float4 a = *(const float4*)(g_ubuf + (size_t)(t * 2) * DIM + d);
    float4 b = *(const float4*)(g_ubuf + (size_t)(t * 2 + 1) * DIM + d);
    float4 z = *(float4*)(out + (size_t)t * DIM + d);
    z.x += w0 * a.x + w1 * b.x;
    z.y += w0 * a.y + w1 * b.y;
    z.z += w0 * a.z + w1 * b.z;
    z.w += w0 * a.w + w1 * b.w;
    *(float4*)(out + (size_t)t * DIM + d) = z;
}

// ---------------- launcher ------------------------------------------------------
extern "C" void kernel_launch(void* const* d_in, const int* in_sizes, int n_in,
                              void* d_out, int out_size)
{
    const float* emb = (const float*)d_in[0];
    const float* x   = (const float*)d_in[1];
    const float* gw  = (const float*)d_in[2];
    const float* W1  = (const float*)d_in[3];
    const float* B1  = (const float*)d_in[4];
    const float* W2  = (const float*)d_in[5];
    const float* B2  = (const float*)d_in[6];
    const float* W3  = (const float*)d_in[7];
    const float* B3  = (const float*)d_in[8];
    const float* sW1 = (const float*)d_in[9];
    const float* sB1 = (const float*)d_in[10];
    const float* sW2 = (const float*)d_in[11];
    const float* sB2 = (const float*)d_in[12];
    float* out = (float*)d_out;

    cudaFuncSetAttribute(k_dense<0>, cudaFuncAttributeMaxDynamicSharedMemorySize, SMEM_GEMM);
    cudaFuncSetAttribute(k_dense<1>, cudaFuncAttributeMaxDynamicSharedMemorySize, SMEM_GEMM);
    cudaFuncSetAttribute(k_moe<0>,   cudaFuncAttributeMaxDynamicSharedMemorySize, SMEM_GEMM);
    cudaFuncSetAttribute(k_moe<1>,   cudaFuncAttributeMaxDynamicSharedMemorySize, SMEM_GEMM);

    float *embr, *xr, *tw1, *tw3, *tw2, *tsw1, *tsw2, *ubuf, *hbuf, *zbuf, *b1g, *b3g;
    cudaGetSymbolAddress((void**)&embr, g_embr);
    cudaGetSymbolAddress((void**)&xr,   g_xr);
    cudaGetSymbolAddress((void**)&tw1,  g_tw1);
    cudaGetSymbolAddress((void**)&tw3,  g_tw3);
    cudaGetSymbolAddress((void**)&tw2,  g_tw2);
    cudaGetSymbolAddress((void**)&tsw1, g_tsw1);
    cudaGetSymbolAddress((void**)&tsw2, g_tsw2);
    cudaGetSymbolAddress((void**)&ubuf, g_ubuf);
    cudaGetSymbolAddress((void**)&hbuf, g_hbuf);
    cudaGetSymbolAddress((void**)&zbuf, g_zbuf);
    (void)b1g; (void)b3g;

    k_zero<<<1, 32>>>();
    k_gate<<<TOK / 4, 128>>>(emb, gw);

    // tf32-round activations
    int n4a = TOK * DIM / 4;
    k_round<<<(n4a + 255) / 256, 256>>>(emb, embr, n4a);
    k_round<<<(n4a + 255) / 256, 256>>>(x,   xr,   n4a);

    // transpose + round weights
    dim3 tb(32, 8);
    k_tr<<<dim3(HID / 32, DIM / 32, NE), tb>>>(W1, tw1, DIM, HID);
    k_tr<<<dim3(HID / 32, DIM / 32, NE), tb>>>(W3, tw3, DIM, HID);
    k_tr<<<dim3(DIM / 32, HID / 32, NE), tb>>>(W2, tw2, HID, DIM);
    k_tr<<<dim3(SHH / 32, DIM / 32, 1),  tb>>>(sW1, tsw1, DIM, SHH);
    k_tr<<<dim3(DIM / 32, SHH / 32, 1),  tb>>>(sW2, tsw2, SHH, DIM);

    // shared expert: zbuf = silu(embr @ tsw1 + sB1); out = zbuf @ tsw2 + sB2
    k_dense<1><<<dim3(SHH / BNT, TOK / BMT), 256, SMEM_GEMM>>>(embr, DIM, tsw1, DIM, sB1, zbuf, SHH);
    k_dense<0><<<dim3(DIM / BNT, TOK / BMT), 256, SMEM_GEMM>>>(zbuf, SHH, tsw2, SHH, sB2, out, DIM);

    // routed experts
    k_moe<0><<<dim3(HID / BNT, TOK / BMT, NE), 256, SMEM_GEMM>>>(xr, embr, tw1, DIM, B1, ubuf, HID);
    k_moe<0><<<dim3(HID / BNT, TOK / BMT, NE), 256, SMEM_GEMM>>>(xr, embr, tw3, DIM, B3, hbuf, HID);
    int n4h = TOK * 2 * HID / 4;
    k_swiglu<<<(n4h + 255) / 256, 256>>>(n4h);
    k_moe<1><<<dim3(DIM / BNT, TOK / BMT, NE), 256, SMEM_GEMM>>>(hbuf, hbuf, tw2, HID, B2, ubuf, DIM);
    k_comb<<<TOK, 256>>>(out);

    (void)in_sizes; (void)n_in; (void)out_size;
}